// round 13
// baseline (speedup 1.0000x reference)
#include <cuda_runtime.h>
#include <cuda_fp16.h>
#include <cstdint>

typedef unsigned long long ull;

#define NMOL 512
#define MA   64
#define F    128
#define NF   16
#define DIN  2176   // F*(1+NF)
#define HID  512

// ======================= helpers =======================
__device__ __forceinline__ uint32_t smem_to_u32(const void* p) {
    uint32_t a;
    asm("{ .reg .u64 t; cvta.to.shared.u64 t, %1; cvt.u32.u64 %0, t; }" : "=r"(a) : "l"(p));
    return a;
}
__device__ __forceinline__ void cpasync16(uint32_t s, const void* g) {
    asm volatile("cp.async.cg.shared.global [%0], [%1], 16;" :: "r"(s), "l"(g) : "memory");
}
__device__ __forceinline__ void cp_commit() { asm volatile("cp.async.commit_group;" ::: "memory"); }
__device__ __forceinline__ void cp_wait0()  { asm volatile("cp.async.wait_group 0;"  ::: "memory"); }

__device__ __forceinline__ void ld4(uint32_t& r0, uint32_t& r1, uint32_t& r2, uint32_t& r3, uint32_t a) {
    asm volatile("ldmatrix.sync.aligned.m8n8.x4.shared.b16 {%0,%1,%2,%3}, [%4];"
                 : "=r"(r0), "=r"(r1), "=r"(r2), "=r"(r3) : "r"(a));
}
__device__ __forceinline__ void ld4t(uint32_t& r0, uint32_t& r1, uint32_t& r2, uint32_t& r3, uint32_t a) {
    asm volatile("ldmatrix.sync.aligned.m8n8.x4.trans.shared.b16 {%0,%1,%2,%3}, [%4];"
                 : "=r"(r0), "=r"(r1), "=r"(r2), "=r"(r3) : "r"(a));
}
// f16 MMA, f32 accumulate: m16n8k16
__device__ __forceinline__ void mma16(float& c0, float& c1, float& c2, float& c3,
                                      uint32_t a0, uint32_t a1, uint32_t a2, uint32_t a3,
                                      uint32_t b0, uint32_t b1) {
    asm volatile("mma.sync.aligned.m16n8k16.row.col.f32.f16.f16.f32 "
                 "{%0,%1,%2,%3}, {%4,%5,%6,%7}, {%8,%9}, {%0,%1,%2,%3};"
                 : "+f"(c0), "+f"(c1), "+f"(c2), "+f"(c3)
                 : "r"(a0), "r"(a1), "r"(a2), "r"(a3), "r"(b0), "r"(b1));
}
__device__ __forceinline__ uint32_t h2u(__half2 h) { return *(uint32_t*)&h; }

// ---------- scratch (device globals: allocation-free) ----------
__device__ __align__(256) __half g_Uh[(size_t)NMOL * MA * NF * F];   // 134 MB
__device__ __align__(256) __half g_Th[(size_t)NMOL * MA * HID];      // 32 MB
__device__ __align__(256) __half g_hh[(size_t)NMOL * MA * F];        // 8 MB
__device__ __align__(256) __half g_W1h[(size_t)DIN * HID];           // 2.2 MB  (k-major, as W1)
__device__ __align__(256) __half g_W2h[(size_t)HID * F];             // 128 KB  (k-major, as W2)

// ---------- K0: copy z (as float) and r into the output buffer ----------
__global__ void k0_copy(const int* __restrict__ z, const float* __restrict__ r,
                        float* __restrict__ oz, float* __restrict__ orr,
                        int nz, int nr) {
    int i = blockIdx.x * blockDim.x + threadIdx.x;
    if (i < nz) oz[i]  = (float)z[i];
    if (i < nr) orr[i] = r[i];
}

// ---------- f32 -> f16 (RNE) convert: h, W1, W2 in one launch ----------
__global__ void kcvt_all(const float* __restrict__ h,  const float* __restrict__ W1,
                         const float* __restrict__ W2, __half* __restrict__ hh,
                         __half* __restrict__ W1h, __half* __restrict__ W2h, int nh)
{
    const int n1 = DIN * HID, n2 = HID * F;
    int i = (blockIdx.x * blockDim.x + threadIdx.x) * 4;
    const float* s; __half* d; int off;
    if (i < nh)                { s = h;  d = hh;  off = 0; }
    else if (i < nh + n1)      { s = W1; d = W1h; off = nh; }
    else if (i < nh + n1 + n2) { s = W2; d = W2h; off = nh + n1; }
    else return;
    int j = i - off;
    float4 v = *(const float4*)(s + j);
    __half2 a = __floats2half2_rn(v.x, v.y);
    __half2 b = __floats2half2_rn(v.z, v.w);
    *(uint2*)(d + j) = make_uint2(h2u(a), h2u(b));
}

// ======================= K1: RBF + aggregation on tensor cores =======================
__global__ __launch_bounds__(256) void k1_tc(
    const int* __restrict__ z, const float* __restrict__ r,
    const float* __restrict__ dist, const float* __restrict__ widths,
    const __half* __restrict__ hh, __half* __restrict__ U)
{
    __shared__ __half sh_h[MA * F];   // 16 KB, swizzled k-major (256B rows)
    __shared__ __half sh_w[MA * MA];  // 8 KB, swizzled row-major (128B rows)
    __shared__ float s_r[192];
    __shared__ float s_m[64];
    int n = blockIdx.x, tid = threadIdx.x;
    int wid = tid >> 5, lane = tid & 31;
    int gid = lane >> 2, tig = lane & 3;
    int warp_m = wid >> 1, warp_n = wid & 1;
    uint32_t hbase = smem_to_u32(sh_h), wbase = smem_to_u32(sh_w);

    {
        const __half* hg = hh + (size_t)n * MA * F;
#pragma unroll
        for (int p = 0; p < 4; p++) {
            int idx = p * 256 + tid;
            int row = idx >> 4, u = idx & 15;
            cpasync16(hbase + row * 256 + ((u ^ (row & 7)) << 4), hg + (size_t)row * F + u * 8);
        }
        cp_commit();
    }
    if (tid < 192) s_r[tid] = r[(size_t)n * 192 + tid];
    if (tid >= 192) s_m[tid - 192] = (z[n * MA + (tid - 192)] > -1) ? 1.0f : 0.0f;
    __syncthreads();

    float d[16];
    {
        int b = tid & 63;
        float bx = s_r[b * 3 + 0], by = s_r[b * 3 + 1], bz = s_r[b * 3 + 2];
        float mb = s_m[b];
#pragma unroll
        for (int q = 0; q < 16; q++) {
            int a = (tid >> 6) + 4 * q;
            float dx = s_r[a * 3 + 0] - bx;
            float dy = s_r[a * 3 + 1] - by;
            float dz = s_r[a * 3 + 2] - bz;
            float dd = sqrtf(dx * dx + dy * dy + dz * dz + 1e-12f);
            if (s_m[a] * mb == 0.0f) dd = 1e9f;
            d[q] = dd;
        }
    }

    int aRow = warp_m * 16 + (lane & 15);
    int aSw  = lane & 7;
    int kuHi = (lane >> 4);
    int bKrl = (lane & 7) + ((lane >> 3) & 1) * 8;
    int bNuL = (lane >> 4);
    int wb   = tid & 63;
    __half* Un = U + (size_t)n * MA * (NF * F);

    for (int f = 0; f < NF; f++) {
        float mu   = __ldg(&dist[f]);
        float isg2 = 1.4426950408889634f / __ldg(&widths[f]);
        __syncthreads();
#pragma unroll
        for (int q = 0; q < 16; q++) {
            int a = (tid >> 6) + 4 * q;
            float t = d[q] - mu;
            __half wv = __float2half_rn(5.0f * exp2f(-t * t * isg2));
            int off = a * 128 + ((((wb >> 3) ^ (a & 7))) << 4) + (wb & 7) * 2;
            *(__half*)((char*)sh_w + off) = wv;
        }
        if (f == 0) cp_wait0();
        __syncthreads();

        float acc[8][4];
#pragma unroll
        for (int nf = 0; nf < 8; nf++)
#pragma unroll
            for (int q = 0; q < 4; q++) acc[nf][q] = 0.0f;

#pragma unroll
        for (int kk = 0; kk < 4; kk++) {
            uint32_t a0, a1, a2, a3;
            uint32_t ad = wbase + aRow * 128 + (((kk * 2 + kuHi) ^ aSw) << 4);
            ld4(a0, a1, a2, a3, ad);
#pragma unroll
            for (int np = 0; np < 4; np++) {
                int krow = kk * 16 + bKrl;
                int nu = warp_n * 8 + np * 2 + bNuL;
                uint32_t bd = hbase + krow * 256 + ((nu ^ (krow & 7)) << 4);
                uint32_t b0, b1r, b2, b3;
                ld4t(b0, b1r, b2, b3, bd);
                int nf0 = np * 2, nf1 = nf0 + 1;
                mma16(acc[nf0][0], acc[nf0][1], acc[nf0][2], acc[nf0][3],
                      a0, a1, a2, a3, b0, b1r);
                mma16(acc[nf1][0], acc[nf1][1], acc[nf1][2], acc[nf1][3],
                      a0, a1, a2, a3, b2, b3);
            }
        }
        int rr = warp_m * 16 + gid;
#pragma unroll
        for (int nf = 0; nf < 8; nf++) {
            int cc = warp_n * 64 + nf * 8 + tig * 2;
            *(uint32_t*)&Un[(size_t)rr * (NF * F) + f * F + cc] =
                h2u(__floats2half2_rn(acc[nf][0], acc[nf][1]));
            *(uint32_t*)&Un[(size_t)(rr + 8) * (NF * F) + f * F + cc] =
                h2u(__floats2half2_rn(acc[nf][2], acc[nf][3]));
        }
    }
}

// ======================= K2: T = silu([h|U] @ W1 + b1) via f16 mma =======================
// BM=128, BN=128, BK=128 halves, 2-stage cp.async, ONE barrier per chunk.
// 512 threads = 16 warps as 4(m) x 4(n); warp tile 32x32 (acc 32 regs).
// Grid = (4, 256) = 1024 CTAs -> 6.9 waves on 148 SMs: tail waste ~1% (vs 15% at 512 CTAs).
#define K2_CHUNKS 17
#define K2_A_BYTES 32768
#define K2_B_BYTES 32768
#define K2_STAGE   (K2_A_BYTES + K2_B_BYTES)   // 65536
#define K2_DYN     (2 * K2_STAGE)              // 131072

__device__ __forceinline__ void k2_load(int j, int row0, int col0,
    const __half* __restrict__ hh, const __half* __restrict__ Uh,
    const __half* __restrict__ W1h, uint32_t sA, uint32_t sB, int tid)
{
    int k0 = j * 128;
    const __half* Ab; size_t lda;
    if (j == 0) { Ab = hh + (size_t)row0 * F;                lda = F; }
    else        { Ab = Uh + (size_t)row0 * 2048 + (k0 - F);  lda = 2048; }
    // A: 128 rows x 128 halves (256B rows, swizzled)
#pragma unroll
    for (int p = 0; p < 4; p++) {
        int idx = p * 512 + tid;
        int m = idx >> 4, u = idx & 15;
        cpasync16(sA + m * 256 + (((u ^ (m & 7))) << 4), Ab + (size_t)m * lda + u * 8);
    }
    // B: 128 k-rows x 128 halves (256B rows, swizzled)
    const __half* Bb = W1h + (size_t)k0 * HID + col0;
#pragma unroll
    for (int p = 0; p < 4; p++) {
        int idx = p * 512 + tid;
        int kr = idx >> 4, u = idx & 15;
        cpasync16(sB + kr * 256 + (((u ^ (kr & 7))) << 4), Bb + (size_t)kr * HID + u * 8);
    }
}

__global__ __launch_bounds__(512, 1) void k2_tc(
    const __half* __restrict__ hh, const __half* __restrict__ Uh,
    const __half* __restrict__ W1h, const float* __restrict__ b1,
    __half* __restrict__ T)
{
    extern __shared__ char dynsm[];
    uint32_t dbase = smem_to_u32(dynsm);
    int tid = threadIdx.x, wid = tid >> 5, lane = tid & 31;
    int gid = lane >> 2, tig = lane & 3;
    int warp_m = wid >> 2, warp_n = wid & 3;     // 4 x 4 warps
    int col0 = blockIdx.x * 128, row0 = blockIdx.y * 128;

    float acc[2][4][4];
#pragma unroll
    for (int mf = 0; mf < 2; mf++)
#pragma unroll
        for (int nf = 0; nf < 4; nf++)
#pragma unroll
            for (int q = 0; q < 4; q++) acc[mf][nf][q] = 0.0f;

    int aRow = warp_m * 32 + (lane & 15);        // + mf*16
    int aSw  = lane & 7;
    int kuHi = (lane >> 4);
    int bKrl = (lane & 7) + ((lane >> 3) & 1) * 8;
    int bNuL = (lane >> 4);

    // prologue: stage 0
    k2_load(0, row0, col0, hh, Uh, W1h, dbase, dbase + K2_A_BYTES, tid);
    cp_commit();

    for (int j = 0; j < K2_CHUNKS; j++) {
        cp_wait0();          // stage j%2 data landed (only outstanding group)
        __syncthreads();     // + all warps done reading stage (j+1)%2 from iter j-1
        if (j + 1 < K2_CHUNKS) {
            uint32_t sN = dbase + ((j + 1) & 1) * K2_STAGE;
            k2_load(j + 1, row0, col0, hh, Uh, W1h, sN, sN + K2_A_BYTES, tid);
            cp_commit();     // overlaps with this chunk's mma
        }
        uint32_t sA = dbase + (j & 1) * K2_STAGE;
        uint32_t sB = sA + K2_A_BYTES;
#pragma unroll
        for (int kk = 0; kk < 8; kk++) {
            uint32_t a[2][4];
#pragma unroll
            for (int mf = 0; mf < 2; mf++) {
                int rowm = aRow + mf * 16;
                uint32_t ad = sA + rowm * 256 + (((kk * 2 + kuHi) ^ aSw) << 4);
                ld4(a[mf][0], a[mf][1], a[mf][2], a[mf][3], ad);
            }
#pragma unroll
            for (int np = 0; np < 2; np++) {
                int krow = kk * 16 + bKrl;
                int nu = warp_n * 4 + np * 2 + bNuL;
                uint32_t bd = sB + krow * 256 + (((nu ^ (krow & 7))) << 4);
                uint32_t b0, b1r, b2, b3;
                ld4t(b0, b1r, b2, b3, bd);
                int nf0 = np * 2, nf1 = nf0 + 1;
#pragma unroll
                for (int mf = 0; mf < 2; mf++) {
                    mma16(acc[mf][nf0][0], acc[mf][nf0][1], acc[mf][nf0][2], acc[mf][nf0][3],
                          a[mf][0], a[mf][1], a[mf][2], a[mf][3], b0, b1r);
                    mma16(acc[mf][nf1][0], acc[mf][nf1][1], acc[mf][nf1][2], acc[mf][nf1][3],
                          a[mf][0], a[mf][1], a[mf][2], a[mf][3], b2, b3);
                }
            }
        }
    }

    // epilogue: bias + silu -> T (half)
#pragma unroll
    for (int mf = 0; mf < 2; mf++) {
        int rr = row0 + warp_m * 32 + mf * 16 + gid;
#pragma unroll
        for (int nf = 0; nf < 4; nf++) {
            int cc = col0 + warp_n * 32 + nf * 8 + tig * 2;
            float ba = __ldg(&b1[cc]), bb = __ldg(&b1[cc + 1]);
            float x0 = acc[mf][nf][0] + ba, x1 = acc[mf][nf][1] + bb;
            float x2 = acc[mf][nf][2] + ba, x3 = acc[mf][nf][3] + bb;
            x0 = x0 / (1.0f + __expf(-x0));
            x1 = x1 / (1.0f + __expf(-x1));
            x2 = x2 / (1.0f + __expf(-x2));
            x3 = x3 / (1.0f + __expf(-x3));
            *(uint32_t*)&T[(size_t)rr * HID + cc]       = h2u(__floats2half2_rn(x0, x1));
            *(uint32_t*)&T[(size_t)(rr + 8) * HID + cc] = h2u(__floats2half2_rn(x2, x3));
        }
    }
}

// ======================= K3: out = h + 0.1*(T @ W2 + b2)*mask via f16 mma =======================
// BM=128, BN=128, BK=128, 2-stage, ONE barrier per chunk. 8 warps 2(m) x 4(n), warp 64x32.
#define K3_CHUNKS 4
#define K3_A_BYTES 32768
#define K3_B_BYTES 32768
#define K3_STAGE   (K3_A_BYTES + K3_B_BYTES)   // 65536
#define K3_DYN     (2 * K3_STAGE)              // 131072

__device__ __forceinline__ void k3_load(int j, int row0,
    const __half* __restrict__ T, const __half* __restrict__ W2h,
    uint32_t sA, uint32_t sB, int tid)
{
    int k0 = j * 128;
    const __half* Ab = T + (size_t)row0 * HID + k0;
#pragma unroll
    for (int p = 0; p < 8; p++) {
        int idx = p * 256 + tid;
        int m = idx >> 4, u = idx & 15;
        cpasync16(sA + m * 256 + (((u ^ (m & 7))) << 4), Ab + (size_t)m * HID + u * 8);
    }
    const __half* Bb = W2h + (size_t)k0 * F;
#pragma unroll
    for (int p = 0; p < 8; p++) {
        int idx = p * 256 + tid;
        int kr = idx >> 4, u = idx & 15;
        cpasync16(sB + kr * 256 + (((u ^ (kr & 7))) << 4), Bb + (size_t)kr * F + u * 8);
    }
}

__global__ __launch_bounds__(256, 1) void k3_tc(
    const __half* __restrict__ T, const __half* __restrict__ W2h,
    const float* __restrict__ b2, const float* __restrict__ h,
    const int* __restrict__ z, float* __restrict__ out)
{
    extern __shared__ char dynsm[];
    uint32_t dbase = smem_to_u32(dynsm);
    int tid = threadIdx.x, wid = tid >> 5, lane = tid & 31;
    int gid = lane >> 2, tig = lane & 3;
    int warp_m = wid >> 2, warp_n = wid & 3;
    int row0 = blockIdx.x * 128;

    float acc[4][4][4];
#pragma unroll
    for (int mf = 0; mf < 4; mf++)
#pragma unroll
        for (int nf = 0; nf < 4; nf++)
#pragma unroll
            for (int q = 0; q < 4; q++) acc[mf][nf][q] = 0.0f;

    int aRow = warp_m * 64 + (lane & 15);
    int aSw  = lane & 7;
    int kuHi = (lane >> 4);
    int bKrl = (lane & 7) + ((lane >> 3) & 1) * 8;
    int bNuL = (lane >> 4);

    k3_load(0, row0, T, W2h, dbase, dbase + K3_A_BYTES, tid);
    cp_commit();

    for (int j = 0; j < K3_CHUNKS; j++) {
        cp_wait0();
        __syncthreads();
        if (j + 1 < K3_CHUNKS) {
            uint32_t sN = dbase + ((j + 1) & 1) * K3_STAGE;
            k3_load(j + 1, row0, T, W2h, sN, sN + K3_A_BYTES, tid);
            cp_commit();
        }
        uint32_t sA = dbase + (j & 1) * K3_STAGE;
        uint32_t sB = sA + K3_A_BYTES;
#pragma unroll
        for (int kk = 0; kk < 8; kk++) {
            uint32_t a[4][4];
#pragma unroll
            for (int mf = 0; mf < 4; mf++) {
                int rowm = aRow + mf * 16;
                uint32_t ad = sA + rowm * 256 + (((kk * 2 + kuHi) ^ aSw) << 4);
                ld4(a[mf][0], a[mf][1], a[mf][2], a[mf][3], ad);
            }
#pragma unroll
            for (int np = 0; np < 2; np++) {
                int krow = kk * 16 + bKrl;
                int nu = warp_n * 4 + np * 2 + bNuL;
                uint32_t bd = sB + krow * 256 + (((nu ^ (krow & 7))) << 4);
                uint32_t b0, b1r, b2, b3;
                ld4t(b0, b1r, b2, b3, bd);
                int nf0 = np * 2, nf1 = nf0 + 1;
#pragma unroll
                for (int mf = 0; mf < 4; mf++) {
                    mma16(acc[mf][nf0][0], acc[mf][nf0][1], acc[mf][nf0][2], acc[mf][nf0][3],
                          a[mf][0], a[mf][1], a[mf][2], a[mf][3], b0, b1r);
                    mma16(acc[mf][nf1][0], acc[mf][nf1][1], acc[mf][nf1][2], acc[mf][nf1][3],
                          a[mf][0], a[mf][1], a[mf][2], a[mf][3], b2, b3);
                }
            }
        }
    }

#pragma unroll
    for (int mf = 0; mf < 4; mf++) {
        int rr = row0 + warp_m * 64 + mf * 16 + gid;
        float m0 = (__ldg(&z[rr])     > -1) ? 0.1f : 0.0f;
        float m8 = (__ldg(&z[rr + 8]) > -1) ? 0.1f : 0.0f;
#pragma unroll
        for (int nf = 0; nf < 4; nf++) {
            int cc = warp_n * 32 + nf * 8 + tig * 2;
            float ba = __ldg(&b2[cc]), bb = __ldg(&b2[cc + 1]);
            float2 h0 = *(const float2*)&h[(size_t)rr * F + cc];
            float2 h8 = *(const float2*)&h[(size_t)(rr + 8) * F + cc];
            float o0 = h0.x + m0 * (acc[mf][nf][0] + ba);
            float o1 = h0.y + m0 * (acc[mf][nf][1] + bb);
            float o2 = h8.x + m8 * (acc[mf][nf][2] + ba);
            float o3 = h8.y + m8 * (acc[mf][nf][3] + bb);
            *(float2*)&out[(size_t)rr * F + cc]       = make_float2(o0, o1);
            *(float2*)&out[(size_t)(rr + 8) * F + cc] = make_float2(o2, o3);
        }
    }
}

extern "C" void kernel_launch(void* const* d_in, const int* in_sizes, int n_in,
                              void* d_out, int out_size)
{
    const int*   z    = (const int*)d_in[0];
    const float* r    = (const float*)d_in[1];
    const float* h    = (const float*)d_in[2];
    const float* dist = (const float*)d_in[3];
    const float* wids = (const float*)d_in[4];
    const float* W1   = (const float*)d_in[5];
    const float* b1   = (const float*)d_in[6];
    const float* W2   = (const float*)d_in[7];
    const float* b2   = (const float*)d_in[8];

    __half *Uh, *Th, *hh, *W1h, *W2h;
    cudaGetSymbolAddress((void**)&Uh,  g_Uh);
    cudaGetSymbolAddress((void**)&Th,  g_Th);
    cudaGetSymbolAddress((void**)&hh,  g_hh);
    cudaGetSymbolAddress((void**)&W1h, g_W1h);
    cudaGetSymbolAddress((void**)&W2h, g_W2h);

    int nz = in_sizes[0], nr = in_sizes[1], nh = in_sizes[2];
    int nmol = nh / (MA * F);            // 512
    int rows = nmol * MA;                // 32768

    float* out   = (float*)d_out;
    float* out_h = out;
    if (out_size == nz + nr + nh) {
        k0_copy<<<(nr + 255) / 256, 256>>>(z, r, out, out + nz, nz, nr);
        out_h = out + nz + nr;
    }

    int ncvt = nh + DIN * HID + HID * F;
    kcvt_all<<<(ncvt / 4 + 255) / 256, 256>>>(h, W1, W2, hh, W1h, W2h, nh);

    k1_tc<<<nmol, 256>>>(z, r, dist, wids, hh, Uh);

    cudaFuncSetAttribute(k2_tc, cudaFuncAttributeMaxDynamicSharedMemorySize, K2_DYN);
    k2_tc<<<dim3(HID / 128, rows / 128), 512, K2_DYN>>>(hh, Uh, W1h, b1, Th);

    cudaFuncSetAttribute(k3_tc, cudaFuncAttributeMaxDynamicSharedMemorySize, K3_DYN);
    k3_tc<<<rows / 128, 256, K3_DYN>>>(Th, W2h, b2, h, z, out_h);
}

// round 14
// speedup vs baseline: 1.0016x; 1.0016x over previous
#include <cuda_runtime.h>
#include <cuda_fp16.h>
#include <cstdint>

#define NMOL 512
#define MA   64
#define F    128
#define NF   16
#define DIN  2176   // F*(1+NF)
#define HID  512

// ======================= helpers =======================
__device__ __forceinline__ uint32_t smem_to_u32(const void* p) {
    uint32_t a;
    asm("{ .reg .u64 t; cvta.to.shared.u64 t, %1; cvt.u32.u64 %0, t; }" : "=r"(a) : "l"(p));
    return a;
}
__device__ __forceinline__ void cpasync16(uint32_t s, const void* g) {
    asm volatile("cp.async.cg.shared.global [%0], [%1], 16;" :: "r"(s), "l"(g) : "memory");
}
__device__ __forceinline__ void cp_commit() { asm volatile("cp.async.commit_group;" ::: "memory"); }
__device__ __forceinline__ void cp_wait0()  { asm volatile("cp.async.wait_group 0;"  ::: "memory"); }

__device__ __forceinline__ void ld4(uint32_t& r0, uint32_t& r1, uint32_t& r2, uint32_t& r3, uint32_t a) {
    asm volatile("ldmatrix.sync.aligned.m8n8.x4.shared.b16 {%0,%1,%2,%3}, [%4];"
                 : "=r"(r0), "=r"(r1), "=r"(r2), "=r"(r3) : "r"(a));
}
__device__ __forceinline__ void ld4t(uint32_t& r0, uint32_t& r1, uint32_t& r2, uint32_t& r3, uint32_t a) {
    asm volatile("ldmatrix.sync.aligned.m8n8.x4.trans.shared.b16 {%0,%1,%2,%3}, [%4];"
                 : "=r"(r0), "=r"(r1), "=r"(r2), "=r"(r3) : "r"(a));
}
// f16 MMA, f32 accumulate: m16n8k16
__device__ __forceinline__ void mma16(float& c0, float& c1, float& c2, float& c3,
                                      uint32_t a0, uint32_t a1, uint32_t a2, uint32_t a3,
                                      uint32_t b0, uint32_t b1) {
    asm volatile("mma.sync.aligned.m16n8k16.row.col.f32.f16.f16.f32 "
                 "{%0,%1,%2,%3}, {%4,%5,%6,%7}, {%8,%9}, {%0,%1,%2,%3};"
                 : "+f"(c0), "+f"(c1), "+f"(c2), "+f"(c3)
                 : "r"(a0), "r"(a1), "r"(a2), "r"(a3), "r"(b0), "r"(b1));
}
__device__ __forceinline__ uint32_t h2u(__half2 h) { return *(uint32_t*)&h; }

// w = 5 * 2^(-u), u in [0, 40], via 2^-u = 2^-n * 0.5 * 2^(1-f), poly for 2.5*2^y on [0,1]
__device__ __forceinline__ float w_exp(float t) {
    const float C0 = 2.4999999255f, C1 = 1.7328826830f, C2 = 0.6003840428f,
                C3 = 0.1395657950f, C4 = 0.0224733505f, C5 = 0.0046939418f;
    float u  = fminf(t, 40.0f);
    float ff = floorf(u);
    int   n  = (int)ff;
    float y  = (ff - u) + 1.0f;          // y = 1 - frac(u), in (0, 1]
    float p  = ((((C5 * y + C4) * y + C3) * y + C2) * y + C1) * y + C0;  // = 2.5 * 2^y
    float sc = __uint_as_float((uint32_t)(127 - n) << 23);               // 2^-n
    return p * sc;                        // = 5 * 2^-u
}

// ---------- scratch (device globals: allocation-free) ----------
__device__ __align__(256) __half g_Uh[(size_t)NMOL * MA * NF * F];   // 134 MB
__device__ __align__(256) __half g_Th[(size_t)NMOL * MA * HID];      // 32 MB
__device__ __align__(256) __half g_hh[(size_t)NMOL * MA * F];        // 8 MB
__device__ __align__(256) __half g_W1h[(size_t)DIN * HID];           // 2.2 MB  (k-major)
__device__ __align__(256) __half g_W2h[(size_t)HID * F];             // 128 KB  (k-major)

// ---------- kprep: z->float copy, r copy, f32->f16 converts, ONE launch ----------
__global__ void kprep(const int* __restrict__ z, const float* __restrict__ r,
                      const float* __restrict__ h,  const float* __restrict__ W1,
                      const float* __restrict__ W2,
                      float* __restrict__ oz, float* __restrict__ orr,
                      __half* __restrict__ hh, __half* __restrict__ W1h,
                      __half* __restrict__ W2h,
                      int nz, int nr, int nh, int ncopy)
{
    const int n1 = DIN * HID, n2 = HID * F;
    int idx = blockIdx.x * blockDim.x + threadIdx.x;
    if (idx < ncopy) {
        if (idx < nz) oz[idx] = (float)z[idx];
        else          orr[idx - nz] = r[idx - nz];
        return;
    }
    int i = (idx - ncopy) * 4;
    const float* s; __half* d; int off;
    if (i < nh)                { s = h;  d = hh;  off = 0; }
    else if (i < nh + n1)      { s = W1; d = W1h; off = nh; }
    else if (i < nh + n1 + n2) { s = W2; d = W2h; off = nh + n1; }
    else return;
    int j = i - off;
    float4 v = *(const float4*)(s + j);
    __half2 a = __floats2half2_rn(v.x, v.y);
    __half2 b = __floats2half2_rn(v.z, v.w);
    *(uint2*)(d + j) = make_uint2(h2u(a), h2u(b));
}

// ======================= K1: RBF + aggregation on tensor cores =======================
// Triangle-symmetric w computation (2080 pairs, mirror-stored), poly exp on FMA pipe,
// double-buffered w tile (one __syncthreads per f).
#define NPAIRS 2080   // 64*65/2

__global__ __launch_bounds__(256) void k1_tc(
    const int* __restrict__ z, const float* __restrict__ r,
    const float* __restrict__ dist, const float* __restrict__ widths,
    const __half* __restrict__ hh, __half* __restrict__ U)
{
    __shared__ __half sh_h[MA * F];       // 16 KB, swizzled k-major (256B rows)
    __shared__ __half sh_w[2][MA * MA];   // 2 x 8 KB, swizzled row-major (128B rows)
    __shared__ float s_r[192];
    __shared__ float s_m[64];
    int n = blockIdx.x, tid = threadIdx.x;
    int wid = tid >> 5, lane = tid & 31;
    int gid = lane >> 2, tig = lane & 3;
    int warp_m = wid >> 1, warp_n = wid & 1;
    uint32_t hbase = smem_to_u32(sh_h), wbase0 = smem_to_u32(sh_w);

    // async-load h tile (64 rows x 256B), swizzled for ld4t
    {
        const __half* hg = hh + (size_t)n * MA * F;
#pragma unroll
        for (int p = 0; p < 4; p++) {
            int idx = p * 256 + tid;
            int row = idx >> 4, u = idx & 15;
            cpasync16(hbase + row * 256 + ((u ^ (row & 7)) << 4), hg + (size_t)row * F + u * 8);
        }
        cp_commit();
    }
    if (tid < 192) s_r[tid] = r[(size_t)n * 192 + tid];
    if (tid >= 192) s_m[tid - 192] = (z[n * MA + (tid - 192)] > -1) ? 1.0f : 0.0f;
    __syncthreads();

    // ---- triangle decode: thread owns pairs i = tid + 256*j, j < NP ----
    // NP = 9 for warp 0 (tid < 32), 8 otherwise (warp-uniform remainder).
    int NP = (tid < (NPAIRS - 256 * 8)) ? 9 : 8;
    float   dd[9];
    uint32_t of1[9], of2[9];
#pragma unroll
    for (int j = 0; j < 9; j++) {
        if (j < NP) {
            int i = tid + 256 * j;
            int q = (int)floorf((sqrtf(8.0f * (float)i + 1.0f) - 1.0f) * 0.5f);
            while (q * (q + 1) / 2 > i) q--;
            while ((q + 1) * (q + 2) / 2 <= i) q++;
            int p = i - q * (q + 1) / 2;     // p <= q
            float dx = s_r[p * 3 + 0] - s_r[q * 3 + 0];
            float dy = s_r[p * 3 + 1] - s_r[q * 3 + 1];
            float dz = s_r[p * 3 + 2] - s_r[q * 3 + 2];
            float d = sqrtf(dx * dx + dy * dy + dz * dz + 1e-12f);
            if (s_m[p] * s_m[q] == 0.0f) d = 1e9f;
            dd[j] = d;
            of1[j] = p * 128 + (((q >> 3) ^ (p & 7)) << 4) + (q & 7) * 2;  // (row p, col q)
            of2[j] = q * 128 + (((p >> 3) ^ (q & 7)) << 4) + (p & 7) * 2;  // (row q, col p)
        }
    }

    // ldmatrix address components (same scheme as k2/k3)
    int aRow = warp_m * 16 + (lane & 15);
    int aSw  = lane & 7;
    int kuHi = (lane >> 4);
    int bKrl = (lane & 7) + ((lane >> 3) & 1) * 8;
    int bNuL = (lane >> 4);
    __half* Un = U + (size_t)n * MA * (NF * F);

    // fill w for f=0 into buffer 0
    {
        float mu   = __ldg(&dist[0]);
        float isg2 = 1.4426950408889634f / __ldg(&widths[0]);
#pragma unroll
        for (int j = 0; j < 9; j++) {
            if (j < NP) {
                float t = dd[j] - mu;
                __half wv = __float2half_rn(w_exp(t * t * isg2));
                *(__half*)((char*)sh_w[0] + of1[j]) = wv;
                *(__half*)((char*)sh_w[0] + of2[j]) = wv;
            }
        }
    }
    cp_wait0();
    __syncthreads();

    for (int f = 0; f < NF; f++) {
        // store w for f+1 into the other buffer (overlaps with this f's mma)
        if (f + 1 < NF) {
            float mu   = __ldg(&dist[f + 1]);
            float isg2 = 1.4426950408889634f / __ldg(&widths[f + 1]);
            char* buf = (char*)sh_w[(f + 1) & 1];
#pragma unroll
            for (int j = 0; j < 9; j++) {
                if (j < NP) {
                    float t = dd[j] - mu;
                    __half wv = __float2half_rn(w_exp(t * t * isg2));
                    *(__half*)(buf + of1[j]) = wv;
                    *(__half*)(buf + of2[j]) = wv;
                }
            }
        }
        uint32_t wbase = wbase0 + (f & 1) * (MA * MA * 2);

        float acc[8][4];
#pragma unroll
        for (int nf = 0; nf < 8; nf++)
#pragma unroll
            for (int q = 0; q < 4; q++) acc[nf][q] = 0.0f;

#pragma unroll
        for (int kk = 0; kk < 4; kk++) {
            uint32_t a0, a1, a2, a3;
            uint32_t ad = wbase + aRow * 128 + (((kk * 2 + kuHi) ^ aSw) << 4);
            ld4(a0, a1, a2, a3, ad);
#pragma unroll
            for (int np = 0; np < 4; np++) {
                int krow = kk * 16 + bKrl;
                int nu = warp_n * 8 + np * 2 + bNuL;
                uint32_t bd = hbase + krow * 256 + ((nu ^ (krow & 7)) << 4);
                uint32_t b0, b1r, b2, b3;
                ld4t(b0, b1r, b2, b3, bd);
                int nf0 = np * 2, nf1 = nf0 + 1;
                mma16(acc[nf0][0], acc[nf0][1], acc[nf0][2], acc[nf0][3],
                      a0, a1, a2, a3, b0, b1r);
                mma16(acc[nf1][0], acc[nf1][1], acc[nf1][2], acc[nf1][3],
                      a0, a1, a2, a3, b2, b3);
            }
        }
        int rr = warp_m * 16 + gid;
#pragma unroll
        for (int nf = 0; nf < 8; nf++) {
            int cc = warp_n * 64 + nf * 8 + tig * 2;
            *(uint32_t*)&Un[(size_t)rr * (NF * F) + f * F + cc] =
                h2u(__floats2half2_rn(acc[nf][0], acc[nf][1]));
            *(uint32_t*)&Un[(size_t)(rr + 8) * (NF * F) + f * F + cc] =
                h2u(__floats2half2_rn(acc[nf][2], acc[nf][3]));
        }
        __syncthreads();   // buf[f&1] reads done; buf[(f+1)&1] stores visible
    }
}

// ======================= K2: T = silu([h|U] @ W1 + b1)  (round-12 best config) =======================
// BM=128, BN=256, BK=128 halves, 2-stage cp.async, ONE barrier per chunk.
// 512 threads = 16 warps as 4(m) x 4(n); warp tile 32x64.
#define K2_CHUNKS 17
#define K2_A_BYTES 32768
#define K2_B_BYTES 65536
#define K2_STAGE   (K2_A_BYTES + K2_B_BYTES)   // 98304
#define K2_DYN     (2 * K2_STAGE)              // 196608

__device__ __forceinline__ void k2_load(int j, int row0, int col0,
    const __half* __restrict__ hh, const __half* __restrict__ Uh,
    const __half* __restrict__ W1h, uint32_t sA, uint32_t sB, int tid)
{
    int k0 = j * 128;
    const __half* Ab; size_t lda;
    if (j == 0) { Ab = hh + (size_t)row0 * F;                lda = F; }
    else        { Ab = Uh + (size_t)row0 * 2048 + (k0 - F);  lda = 2048; }
#pragma unroll
    for (int p = 0; p < 4; p++) {
        int idx = p * 512 + tid;
        int m = idx >> 4, u = idx & 15;
        cpasync16(sA + m * 256 + (((u ^ (m & 7))) << 4), Ab + (size_t)m * lda + u * 8);
    }
    const __half* Bb = W1h + (size_t)k0 * HID + col0;
#pragma unroll
    for (int p = 0; p < 8; p++) {
        int idx = p * 512 + tid;
        int kr = idx >> 5, u = idx & 31;
        cpasync16(sB + kr * 512 + (((u ^ (kr & 7))) << 4), Bb + (size_t)kr * HID + u * 8);
    }
}

__global__ __launch_bounds__(512, 1) void k2_tc(
    const __half* __restrict__ hh, const __half* __restrict__ Uh,
    const __half* __restrict__ W1h, const float* __restrict__ b1,
    __half* __restrict__ T)
{
    extern __shared__ char dynsm[];
    uint32_t dbase = smem_to_u32(dynsm);
    int tid = threadIdx.x, wid = tid >> 5, lane = tid & 31;
    int gid = lane >> 2, tig = lane & 3;
    int warp_m = wid >> 2, warp_n = wid & 3;
    int col0 = blockIdx.x * 256, row0 = blockIdx.y * 128;

    float acc[2][8][4];
#pragma unroll
    for (int mf = 0; mf < 2; mf++)
#pragma unroll
        for (int nf = 0; nf < 8; nf++)
#pragma unroll
            for (int q = 0; q < 4; q++) acc[mf][nf][q] = 0.0f;

    int aRow = warp_m * 32 + (lane & 15);
    int aSw  = lane & 7;
    int kuHi = (lane >> 4);
    int bKrl = (lane & 7) + ((lane >> 3) & 1) * 8;
    int bNuL = (lane >> 4);

    k2_load(0, row0, col0, hh, Uh, W1h, dbase, dbase + K2_A_BYTES, tid);
    cp_commit();

    for (int j = 0; j < K2_CHUNKS; j++) {
        cp_wait0();
        __syncthreads();
        if (j + 1 < K2_CHUNKS) {
            uint32_t sN = dbase + ((j + 1) & 1) * K2_STAGE;
            k2_load(j + 1, row0, col0, hh, Uh, W1h, sN, sN + K2_A_BYTES, tid);
            cp_commit();
        }
        uint32_t sA = dbase + (j & 1) * K2_STAGE;
        uint32_t sB = sA + K2_A_BYTES;
#pragma unroll
        for (int kk = 0; kk < 8; kk++) {
            uint32_t a[2][4];
#pragma unroll
            for (int mf = 0; mf < 2; mf++) {
                int rowm = aRow + mf * 16;
                uint32_t ad = sA + rowm * 256 + (((kk * 2 + kuHi) ^ aSw) << 4);
                ld4(a[mf][0], a[mf][1], a[mf][2], a[mf][3], ad);
            }
#pragma unroll
            for (int np = 0; np < 4; np++) {
                int krow = kk * 16 + bKrl;
                int nu = warp_n * 8 + np * 2 + bNuL;
                uint32_t bd = sB + krow * 512 + (((nu ^ (krow & 7))) << 4);
                uint32_t b0, b1r, b2, b3;
                ld4t(b0, b1r, b2, b3, bd);
                int nf0 = np * 2, nf1 = nf0 + 1;
#pragma unroll
                for (int mf = 0; mf < 2; mf++) {
                    mma16(acc[mf][nf0][0], acc[mf][nf0][1], acc[mf][nf0][2], acc[mf][nf0][3],
                          a[mf][0], a[mf][1], a[mf][2], a[mf][3], b0, b1r);
                    mma16(acc[mf][nf1][0], acc[mf][nf1][1], acc[mf][nf1][2], acc[mf][nf1][3],
                          a[mf][0], a[mf][1], a[mf][2], a[mf][3], b2, b3);
                }
            }
        }
    }

#pragma unroll
    for (int mf = 0; mf < 2; mf++) {
        int rr = row0 + warp_m * 32 + mf * 16 + gid;
#pragma unroll
        for (int nf = 0; nf < 8; nf++) {
            int cc = col0 + warp_n * 64 + nf * 8 + tig * 2;
            float ba = __ldg(&b1[cc]), bb = __ldg(&b1[cc + 1]);
            float x0 = acc[mf][nf][0] + ba, x1 = acc[mf][nf][1] + bb;
            float x2 = acc[mf][nf][2] + ba, x3 = acc[mf][nf][3] + bb;
            x0 = x0 / (1.0f + __expf(-x0));
            x1 = x1 / (1.0f + __expf(-x1));
            x2 = x2 / (1.0f + __expf(-x2));
            x3 = x3 / (1.0f + __expf(-x3));
            *(uint32_t*)&T[(size_t)rr * HID + cc]       = h2u(__floats2half2_rn(x0, x1));
            *(uint32_t*)&T[(size_t)(rr + 8) * HID + cc] = h2u(__floats2half2_rn(x2, x3));
        }
    }
}

// ======================= K3: out = h + 0.1*(T @ W2 + b2)*mask =======================
#define K3_CHUNKS 4
#define K3_A_BYTES 32768
#define K3_B_BYTES 32768
#define K3_STAGE   (K3_A_BYTES + K3_B_BYTES)
#define K3_DYN     (2 * K3_STAGE)

__device__ __forceinline__ void k3_load(int j, int row0,
    const __half* __restrict__ T, const __half* __restrict__ W2h,
    uint32_t sA, uint32_t sB, int tid)
{
    int k0 = j * 128;
    const __half* Ab = T + (size_t)row0 * HID + k0;
#pragma unroll
    for (int p = 0; p < 8; p++) {
        int idx = p * 256 + tid;
        int m = idx >> 4, u = idx & 15;
        cpasync16(sA + m * 256 + (((u ^ (m & 7))) << 4), Ab + (size_t)m * HID + u * 8);
    }
    const __half* Bb = W2h + (size_t)k0 * F;
#pragma unroll
    for (int p = 0; p < 8; p++) {
        int idx = p * 256 + tid;
        int kr = idx >> 4, u = idx & 15;
        cpasync16(sB + kr * 256 + (((u ^ (kr & 7))) << 4), Bb + (size_t)kr * F + u * 8);
    }
}

__global__ __launch_bounds__(256, 1) void k3_tc(
    const __half* __restrict__ T, const __half* __restrict__ W2h,
    const float* __restrict__ b2, const float* __restrict__ h,
    const int* __restrict__ z, float* __restrict__ out)
{
    extern __shared__ char dynsm[];
    uint32_t dbase = smem_to_u32(dynsm);
    int tid = threadIdx.x, wid = tid >> 5, lane = tid & 31;
    int gid = lane >> 2, tig = lane & 3;
    int warp_m = wid >> 2, warp_n = wid & 3;
    int row0 = blockIdx.x * 128;

    float acc[4][4][4];
#pragma unroll
    for (int mf = 0; mf < 4; mf++)
#pragma unroll
        for (int nf = 0; nf < 4; nf++)
#pragma unroll
            for (int q = 0; q < 4; q++) acc[mf][nf][q] = 0.0f;

    int aRow = warp_m * 64 + (lane & 15);
    int aSw  = lane & 7;
    int kuHi = (lane >> 4);
    int bKrl = (lane & 7) + ((lane >> 3) & 1) * 8;
    int bNuL = (lane >> 4);

    k3_load(0, row0, T, W2h, dbase, dbase + K3_A_BYTES, tid);
    cp_commit();

    for (int j = 0; j < K3_CHUNKS; j++) {
        cp_wait0();
        __syncthreads();
        if (j + 1 < K3_CHUNKS) {
            uint32_t sN = dbase + ((j + 1) & 1) * K3_STAGE;
            k3_load(j + 1, row0, T, W2h, sN, sN + K3_A_BYTES, tid);
            cp_commit();
        }
        uint32_t sA = dbase + (j & 1) * K3_STAGE;
        uint32_t sB = sA + K3_A_BYTES;
#pragma unroll
        for (int kk = 0; kk < 8; kk++) {
            uint32_t a[4][4];
#pragma unroll
            for (int mf = 0; mf < 4; mf++) {
                int rowm = aRow + mf * 16;
                uint32_t ad = sA + rowm * 256 + (((kk * 2 + kuHi) ^ aSw) << 4);
                ld4(a[mf][0], a[mf][1], a[mf][2], a[mf][3], ad);
            }
#pragma unroll
            for (int np = 0; np < 2; np++) {
                int krow = kk * 16 + bKrl;
                int nu = warp_n * 4 + np * 2 + bNuL;
                uint32_t bd = sB + krow * 256 + (((nu ^ (krow & 7))) << 4);
                uint32_t b0, b1r, b2, b3;
                ld4t(b0, b1r, b2, b3, bd);
                int nf0 = np * 2, nf1 = nf0 + 1;
#pragma unroll
                for (int mf = 0; mf < 4; mf++) {
                    mma16(acc[mf][nf0][0], acc[mf][nf0][1], acc[mf][nf0][2], acc[mf][nf0][3],
                          a[mf][0], a[mf][1], a[mf][2], a[mf][3], b0, b1r);
                    mma16(acc[mf][nf1][0], acc[mf][nf1][1], acc[mf][nf1][2], acc[mf][nf1][3],
                          a[mf][0], a[mf][1], a[mf][2], a[mf][3], b2, b3);
                }
            }
        }
    }

#pragma unroll
    for (int mf = 0; mf < 4; mf++) {
        int rr = row0 + warp_m * 64 + mf * 16 + gid;
        float m0 = (__ldg(&z[rr])     > -1) ? 0.1f : 0.0f;
        float m8 = (__ldg(&z[rr + 8]) > -1) ? 0.1f : 0.0f;
#pragma unroll
        for (int nf = 0; nf < 4; nf++) {
            int cc = warp_n * 32 + nf * 8 + tig * 2;
            float ba = __ldg(&b2[cc]), bb = __ldg(&b2[cc + 1]);
            float2 h0 = *(const float2*)&h[(size_t)rr * F + cc];
            float2 h8 = *(const float2*)&h[(size_t)(rr + 8) * F + cc];
            float o0 = h0.x + m0 * (acc[mf][nf][0] + ba);
            float o1 = h0.y + m0 * (acc[mf][nf][1] + bb);
            float o2 = h8.x + m8 * (acc[mf][nf][2] + ba);
            float o3 = h8.y + m8 * (acc[mf][nf][3] + bb);
            *(float2*)&out[(size_t)rr * F + cc]       = make_float2(o0, o1);
            *(float2*)&out[(size_t)(rr + 8) * F + cc] = make_float2(o2, o3);
        }
    }
}

extern "C" void kernel_launch(void* const* d_in, const int* in_sizes, int n_in,
                              void* d_out, int out_size)
{
    const int*   z    = (const int*)d_in[0];
    const float* r    = (const float*)d_in[1];
    const float* h    = (const float*)d_in[2];
    const float* dist = (const float*)d_in[3];
    const float* wids = (const float*)d_in[4];
    const float* W1   = (const float*)d_in[5];
    const float* b1   = (const float*)d_in[6];
    const float* W2   = (const float*)d_in[7];
    const float* b2   = (const float*)d_in[8];

    __half *Uh, *Th, *hh, *W1h, *W2h;
    cudaGetSymbolAddress((void**)&Uh,  g_Uh);
    cudaGetSymbolAddress((void**)&Th,  g_Th);
    cudaGetSymbolAddress((void**)&hh,  g_hh);
    cudaGetSymbolAddress((void**)&W1h, g_W1h);
    cudaGetSymbolAddress((void**)&W2h, g_W2h);

    int nz = in_sizes[0], nr = in_sizes[1], nh = in_sizes[2];
    int nmol = nh / (MA * F);            // 512
    int rows = nmol * MA;                // 32768

    float* out   = (float*)d_out;
    float* out_h = out;
    int ncopy = 0;
    float *oz = nullptr, *orr = nullptr;
    if (out_size == nz + nr + nh) {
        ncopy = nz + nr;
        oz  = out;
        orr = out + nz;
        out_h = out + nz + nr;
    }

    int ncvt4 = (nh + DIN * HID + HID * F) / 4;
    int ntot  = ncopy + ncvt4;
    kprep<<<(ntot + 255) / 256, 256>>>(z, r, h, W1, W2, oz, orr, hh, W1h, W2h,
                                       nz, nr, nh, ncopy);

    k1_tc<<<nmol, 256>>>(z, r, dist, wids, hh, Uh);

    cudaFuncSetAttribute(k2_tc, cudaFuncAttributeMaxDynamicSharedMemorySize, K2_DYN);
    k2_tc<<<dim3(HID / 256, rows / 128), 512, K2_DYN>>>(hh, Uh, W1h, b1, Th);

    cudaFuncSetAttribute(k3_tc, cudaFuncAttributeMaxDynamicSharedMemorySize, K3_DYN);
    k3_tc<<<rows / 128, 256, K3_DYN>>>(Th, W2h, b2, h, z, out_h);
}